// round 2
// baseline (speedup 1.0000x reference)
#include <cuda_runtime.h>
#include <math.h>

#define THREADS 256
#define WARPS (THREADS / 32)

// GLIF single timestep, fused matvec + elementwise.
// One CTA per neuron (row of w). out[0:N) = v_new, out[N:2N) = spiked_soft.
__global__ __launch_bounds__(THREADS, 8)
void glif_kernel(const float* __restrict__ x_in,
                 const float* __restrict__ w,
                 const float* __restrict__ v0,
                 const float* __restrict__ g,
                 const float* __restrict__ v_rest,
                 const float* __restrict__ tau_m,
                 const float* __restrict__ theta_s,
                 const float* __restrict__ theta_v,
                 float* __restrict__ out,
                 int n)
{
    const int row = blockIdx.x;
    const int tid = threadIdx.x;

    const float4* __restrict__ wrow =
        reinterpret_cast<const float4*>(w + (size_t)row * (size_t)n);
    const float4* __restrict__ g4 = reinterpret_cast<const float4*>(g);

    const int nvec = n >> 2;  // n/4 float4 per row (n = 8192 -> 2048)

    float acc = 0.0f;
    // 2048 / 256 = 8 vec-iterations per thread; unrolled for MLP.
    #pragma unroll 8
    for (int j = tid; j < nvec; j += THREADS) {
        float4 wv = wrow[j];
        float4 gv = g4[j];
        acc = fmaf(wv.x, gv.x, acc);
        acc = fmaf(wv.y, gv.y, acc);
        acc = fmaf(wv.z, gv.z, acc);
        acc = fmaf(wv.w, gv.w, acc);
    }

    // Warp reduction
    #pragma unroll
    for (int off = 16; off > 0; off >>= 1)
        acc += __shfl_xor_sync(0xFFFFFFFFu, acc, off);

    __shared__ float warp_sums[WARPS];
    if ((tid & 31) == 0) warp_sums[tid >> 5] = acc;
    __syncthreads();

    if (tid == 0) {
        float s = 0.0f;
        #pragma unroll
        for (int wgi = 0; wgi < WARPS; wgi++) s += warp_sums[wgi];

        // GLIF elementwise epilogue for this neuron
        const float xi  = x_in[row];
        const float vr  = v_rest[row];
        const float tm  = tau_m[row];
        const float ths = theta_s[row];
        const float thv = theta_v[row];
        const float vin = v0[row];

        // I = sigmoid(w@g + x_in)
        const float z = s + xi;
        const float I = 1.0f / (1.0f + expf(-z));

        // membrane integration
        const float v = vin + (vr - vin + I) / tm;

        const float thresh = ths + thv;
        // surrogate spike (accurate exp: value can be ~1e-20, rel-err matters)
        const float spiked_soft = 1.0f / (1.0f + expf(-(v - thresh)));
        // hard spike + reset-or-keep
        const float v_new = (v >= thresh) ? vr : v;

        out[row]     = v_new;
        out[n + row] = spiked_soft;
    }
}

extern "C" void kernel_launch(void* const* d_in, const int* in_sizes, int n_in,
                              void* d_out, int out_size)
{
    // metadata order: x_in, w, v, g, v_rest, tau_m, tau_g, theta_s, theta_v, b_s, a_v, b_v
    const float* x_in    = (const float*)d_in[0];
    const float* w       = (const float*)d_in[1];
    const float* v       = (const float*)d_in[2];
    const float* g       = (const float*)d_in[3];
    const float* v_rest  = (const float*)d_in[4];
    const float* tau_m   = (const float*)d_in[5];
    // d_in[6] = tau_g (unused by returned outputs)
    const float* theta_s = (const float*)d_in[7];
    const float* theta_v = (const float*)d_in[8];
    // d_in[9..11] = b_s, a_v, b_v (only affect discarded hidden state)

    float* out = (float*)d_out;
    const int n = in_sizes[0];  // 8192

    glif_kernel<<<n, THREADS>>>(x_in, w, v, g, v_rest, tau_m,
                                theta_s, theta_v, out, n);
}